// round 1
// baseline (speedup 1.0000x reference)
#include <cuda_runtime.h>
#include <cstdint>

// Problem constants
#define Bc   4
#define Nseq 2048
#define Cdim 768
#define Hh   12
#define Dd   64
// SCALE = D = 64, mask factor = -1e6

// Scratch (device globals; no allocation allowed)
__device__ float g_qkv[(size_t)3 * Bc * Hh * Nseq * Dd];   // [3][B][H][N][D]  ~75.5 MB
__device__ float g_ao[(size_t)Bc * Nseq * Cdim];           // [B][N][C]        ~25 MB

// ---------------------------------------------------------------------------
// GEMM NT: C[M,N] = A[M,K] * B[N,K]^T   (both operands K-contiguous)
// MODE 1: A = x, epilogue scatters into g_qkv [3][B][H][N][D]
// MODE 2: A = g_ao (internal), epilogue adds bias and writes C (= d_out)
// ---------------------------------------------------------------------------
#define GBM 128
#define GBN 128
#define GBK 16
#define GPAD 4

template<int MODE>
__global__ void __launch_bounds__(256) gemm_nt(const float* __restrict__ A,
                                               const float* __restrict__ Bm,
                                               const float* __restrict__ bias,
                                               float* __restrict__ C,
                                               int M, int N, int K) {
    __shared__ float As[GBK][GBM + GPAD];
    __shared__ float Bs[GBK][GBN + GPAD];
    const int t  = threadIdx.x;
    const int tx = t & 15;
    const int ty = t >> 4;
    const int i0 = blockIdx.y * GBM;
    const int j0 = blockIdx.x * GBN;
    const float* __restrict__ Ap = (MODE == 2) ? g_ao : A;

    float acc[8][8];
#pragma unroll
    for (int i = 0; i < 8; i++)
#pragma unroll
        for (int j = 0; j < 8; j++) acc[i][j] = 0.f;

    for (int k0 = 0; k0 < K; k0 += GBK) {
        // load A-tile and B-tile (transposed into [k][row] layout)
#pragma unroll
        for (int it = 0; it < 2; ++it) {
            int f4  = t + it * 256;          // 0..511 float4 slots
            int row = f4 >> 2;               // 128 rows, 4 float4 per row
            int kk  = (f4 & 3) << 2;
            float4 va = *(const float4*)(Ap + (size_t)(i0 + row) * K + k0 + kk);
            As[kk + 0][row] = va.x; As[kk + 1][row] = va.y;
            As[kk + 2][row] = va.z; As[kk + 3][row] = va.w;
            float4 vb = *(const float4*)(Bm + (size_t)(j0 + row) * K + k0 + kk);
            Bs[kk + 0][row] = vb.x; Bs[kk + 1][row] = vb.y;
            Bs[kk + 2][row] = vb.z; Bs[kk + 3][row] = vb.w;
        }
        __syncthreads();

#pragma unroll
        for (int kk = 0; kk < GBK; ++kk) {
            float4 a0 = *(const float4*)&As[kk][ty * 8];
            float4 a1 = *(const float4*)&As[kk][ty * 8 + 4];
            float4 b0 = *(const float4*)&Bs[kk][tx * 8];
            float4 b1 = *(const float4*)&Bs[kk][tx * 8 + 4];
            float av[8] = {a0.x, a0.y, a0.z, a0.w, a1.x, a1.y, a1.z, a1.w};
            float bv[8] = {b0.x, b0.y, b0.z, b0.w, b1.x, b1.y, b1.z, b1.w};
#pragma unroll
            for (int i = 0; i < 8; i++)
#pragma unroll
                for (int j = 0; j < 8; j++) acc[i][j] += av[i] * bv[j];
        }
        __syncthreads();
    }

    if (MODE == 1) {
        // scatter into g_qkv [3][B][H][N][D]
#pragma unroll
        for (int i = 0; i < 8; i++) {
            int gi = i0 + ty * 8 + i;
            int b  = gi >> 11;          // /2048
            int n  = gi & 2047;
#pragma unroll
            for (int j = 0; j < 8; j++) {
                int gj    = j0 + tx * 8 + j;
                int three = gj / Cdim;
                int rem   = gj - three * Cdim;
                int h     = rem >> 6;
                int d     = rem & 63;
                g_qkv[((((size_t)three * Bc + b) * Hh + h) * Nseq + n) * Dd + d] = acc[i][j];
            }
        }
    } else {
#pragma unroll
        for (int i = 0; i < 8; i++) {
            int gi = i0 + ty * 8 + i;
#pragma unroll
            for (int j = 0; j < 8; j += 4) {
                int gj = j0 + tx * 8 + j;
                float4 v;
                v.x = acc[i][j + 0] + bias[gj + 0];
                v.y = acc[i][j + 1] + bias[gj + 1];
                v.z = acc[i][j + 2] + bias[gj + 2];
                v.w = acc[i][j + 3] + bias[gj + 3];
                *(float4*)(C + (size_t)gi * N + gj) = v;
            }
        }
    }
}

// ---------------------------------------------------------------------------
// Fused attention: per CTA (b,h, 64-query tile). fp32 throughout.
// logits = 64 * (q.k) - 1e6 * mask ; online softmax ; O += P V
// ---------------------------------------------------------------------------
#define QT 64
#define KT 64
#define SP 68   // padded row stride for transposed smem tiles
#define ATTN_SMEM_FLOATS (3 * 64 * SP + 64 * 64)
#define ATTN_SMEM_BYTES  (ATTN_SMEM_FLOATS * 4)

__global__ void __launch_bounds__(256) attn_kernel(const int* __restrict__ mask) {
    extern __shared__ float sm[];
    float* Qst = sm;                 // [d][row]  (transposed), stride SP
    float* Kst = sm + 64 * SP;       // [d][key]  (transposed), stride SP
    float* Pst = sm + 2 * 64 * SP;   // [key][row](transposed), stride SP
    float* Vs  = sm + 3 * 64 * SP;   // [key][d]  natural, stride 64

    const int bh    = blockIdx.y;           // b*12 + h
    const int b     = bh / Hh;
    const int h     = bh - b * Hh;
    const int qbase = blockIdx.x * QT;
    const float* __restrict__ Qp = g_qkv + (size_t)bh * Nseq * Dd;
    const float* __restrict__ Kp = g_qkv + ((size_t)(Bc * Hh) + bh) * Nseq * Dd;
    const float* __restrict__ Vp = g_qkv + ((size_t)(2 * Bc * Hh) + bh) * Nseq * Dd;

    const int t  = threadIdx.x;
    const int tx = t & 15;
    const int ty = t >> 4;

    // load Q tile transposed
#pragma unroll
    for (int it = 0; it < 4; ++it) {
        int f4    = t + it * 256;     // 1024 float4 slots
        int row   = f4 >> 4;          // 16 float4 per row of 64
        int dbase = (f4 & 15) << 2;
        float4 v = *(const float4*)(Qp + (size_t)(qbase + row) * Dd + dbase);
        Qst[(dbase + 0) * SP + row] = v.x;
        Qst[(dbase + 1) * SP + row] = v.y;
        Qst[(dbase + 2) * SP + row] = v.z;
        Qst[(dbase + 3) * SP + row] = v.w;
    }

    float O[4][4];
    float m_i[4], l_i[4];
#pragma unroll
    for (int i = 0; i < 4; i++) {
        m_i[i] = -1e30f; l_i[i] = 0.f;
#pragma unroll
        for (int j = 0; j < 4; j++) O[i][j] = 0.f;
    }

    for (int kc = 0; kc < Nseq / KT; ++kc) {
        const int kbase = kc * KT;
        __syncthreads();   // previous P·V done reading Vs/Pst
        // load K (transposed) and V (natural)
#pragma unroll
        for (int it = 0; it < 4; ++it) {
            int f4    = t + it * 256;
            int row   = f4 >> 4;
            int dbase = (f4 & 15) << 2;
            float4 kv = *(const float4*)(Kp + (size_t)(kbase + row) * Dd + dbase);
            Kst[(dbase + 0) * SP + row] = kv.x;
            Kst[(dbase + 1) * SP + row] = kv.y;
            Kst[(dbase + 2) * SP + row] = kv.z;
            Kst[(dbase + 3) * SP + row] = kv.w;
            float4 vv = *(const float4*)(Vp + (size_t)(kbase + row) * Dd + dbase);
            *(float4*)(Vs + row * Dd + dbase) = vv;
        }
        __syncthreads();

        // S = Q K^T  (64x64x64)
        float S[4][4];
#pragma unroll
        for (int i = 0; i < 4; i++)
#pragma unroll
            for (int j = 0; j < 4; j++) S[i][j] = 0.f;
#pragma unroll 16
        for (int k = 0; k < Dd; ++k) {
            float4 qf = *(const float4*)&Qst[k * SP + ty * 4];
            float4 kf = *(const float4*)&Kst[k * SP + tx * 4];
            float qa[4] = {qf.x, qf.y, qf.z, qf.w};
            float ka[4] = {kf.x, kf.y, kf.z, kf.w};
#pragma unroll
            for (int i = 0; i < 4; i++)
#pragma unroll
                for (int j = 0; j < 4; j++) S[i][j] += qa[i] * ka[j];
        }

        // logits + mask, online softmax
        float P[4][4], rmax[4];
#pragma unroll
        for (int i = 0; i < 4; i++) {
            int qr = qbase + ty * 4 + i;
            int4 mk = *(const int4*)(mask + (size_t)qr * Nseq + kbase + tx * 4);
            P[i][0] = S[i][0] * 64.f + (float)mk.x * -1.0e6f;
            P[i][1] = S[i][1] * 64.f + (float)mk.y * -1.0e6f;
            P[i][2] = S[i][2] * 64.f + (float)mk.z * -1.0e6f;
            P[i][3] = S[i][3] * 64.f + (float)mk.w * -1.0e6f;
            rmax[i] = fmaxf(fmaxf(P[i][0], P[i][1]), fmaxf(P[i][2], P[i][3]));
        }
#pragma unroll
        for (int off = 8; off; off >>= 1)
#pragma unroll
            for (int i = 0; i < 4; i++)
                rmax[i] = fmaxf(rmax[i], __shfl_xor_sync(0xffffffffu, rmax[i], off));

#pragma unroll
        for (int i = 0; i < 4; i++) {
            float mnew  = fmaxf(m_i[i], rmax[i]);
            float alpha = __expf(m_i[i] - mnew);
            m_i[i] = mnew;
            float rs = 0.f;
#pragma unroll
            for (int j = 0; j < 4; j++) { P[i][j] = __expf(P[i][j] - mnew); rs += P[i][j]; }
#pragma unroll
            for (int off = 8; off; off >>= 1) rs += __shfl_xor_sync(0xffffffffu, rs, off);
            l_i[i] = l_i[i] * alpha + rs;
#pragma unroll
            for (int j = 0; j < 4; j++) O[i][j] *= alpha;
#pragma unroll
            for (int j = 0; j < 4; j++) Pst[(tx * 4 + j) * SP + ty * 4 + i] = P[i][j];
        }
        __syncthreads();

        // O += P V   (64x64x64)
#pragma unroll 16
        for (int c = 0; c < KT; ++c) {
            float4 pf = *(const float4*)&Pst[c * SP + ty * 4];
            float4 vf = *(const float4*)&Vs[c * Dd + tx * 4];
            float pa[4] = {pf.x, pf.y, pf.z, pf.w};
            float va[4] = {vf.x, vf.y, vf.z, vf.w};
#pragma unroll
            for (int i = 0; i < 4; i++)
#pragma unroll
                for (int j = 0; j < 4; j++) O[i][j] += pa[i] * va[j];
        }
    }

    // write to g_ao [B][N][C], layout (b, n, h*64 + d)
#pragma unroll
    for (int i = 0; i < 4; i++) {
        float inv = 1.f / l_i[i];
        int n = qbase + ty * 4 + i;
        float4 o;
        o.x = O[i][0] * inv; o.y = O[i][1] * inv;
        o.z = O[i][2] * inv; o.w = O[i][3] * inv;
        *(float4*)(g_ao + (size_t)(b * Nseq + n) * Cdim + h * Dd + tx * 4) = o;
    }
}

// ---------------------------------------------------------------------------
extern "C" void kernel_launch(void* const* d_in, const int* in_sizes, int n_in,
                              void* d_out, int out_size) {
    const float* x      = (const float*)d_in[0];
    const int*   mask   = (const int*)  d_in[1];
    const float* qkv_w  = (const float*)d_in[2];
    const float* proj_w = (const float*)d_in[3];
    const float* proj_b = (const float*)d_in[4];
    float*       out    = (float*)d_out;

    cudaFuncSetAttribute(attn_kernel,
                         cudaFuncAttributeMaxDynamicSharedMemorySize, ATTN_SMEM_BYTES);

    const int M = Bc * Nseq;  // 8192
    // 1) QKV projection: [8192,768] x [2304,768]^T -> scatter to g_qkv
    gemm_nt<1><<<dim3((3 * Cdim) / GBN, M / GBM), 256>>>(x, qkv_w, nullptr, nullptr,
                                                         M, 3 * Cdim, Cdim);
    // 2) fused attention
    attn_kernel<<<dim3(Nseq / QT, Bc * Hh), 256, ATTN_SMEM_BYTES>>>(mask);
    // 3) output projection + bias
    gemm_nt<2><<<dim3(Cdim / GBN, M / GBM), 256>>>(nullptr, proj_w, proj_b, out,
                                                   M, Cdim, Cdim);
}

// round 3
// speedup vs baseline: 1.2099x; 1.2099x over previous
#include <cuda_runtime.h>
#include <cstdint>

#define Bc   4
#define Nseq 2048
#define Cdim 768
#define Hh   12
#define Dd   64

using u64 = unsigned long long;

__device__ __forceinline__ u64 fma2(u64 a, u64 b, u64 c) {
    u64 d; asm("fma.rn.f32x2 %0,%1,%2,%3;" : "=l"(d) : "l"(a), "l"(b), "l"(c)); return d;
}
__device__ __forceinline__ u64 mul2(u64 a, u64 b) {
    u64 d; asm("mul.rn.f32x2 %0,%1,%2;" : "=l"(d) : "l"(a), "l"(b)); return d;
}
__device__ __forceinline__ u64 pk2(float x, float y) {
    u64 r; asm("mov.b64 %0,{%1,%2};" : "=l"(r) : "f"(x), "f"(y)); return r;
}
__device__ __forceinline__ float2 upk(u64 v) {
    float2 f; asm("mov.b64 {%0,%1},%2;" : "=f"(f.x), "=f"(f.y) : "l"(v)); return f;
}
__device__ __forceinline__ float ex2(float x) {
    float y; asm("ex2.approx.f32 %0,%1;" : "=f"(y) : "f"(x)); return y;
}

__device__ float g_qkv[(size_t)3 * Bc * Hh * Nseq * Dd];   // [3][B][H][N][D]
__device__ float g_ao[(size_t)Bc * Nseq * Cdim];           // [B][N][C]

// ---------------------------------------------------------------------------
// GEMM NT (f32x2): C[M,N] = A[M,K] * B[N,K]^T. 128x128x16, 256 thr, 8x8/thr.
// MODE 1: scatter to g_qkv. MODE 2: A=g_ao, +bias, write C.
// ---------------------------------------------------------------------------
template<int MODE>
__global__ void __launch_bounds__(256, 2) gemm_nt(const float* __restrict__ A,
                                                  const float* __restrict__ Bm,
                                                  const float* __restrict__ bias,
                                                  float* __restrict__ C,
                                                  int M, int N, int K) {
    __shared__ float As[16 * 128];
    __shared__ float Bs[16 * 128];
    const int t  = threadIdx.x;
    const int tx = t & 15, ty = t >> 4;
    const int i0 = blockIdx.y * 128, j0 = blockIdx.x * 128;
    const float* __restrict__ Ap = (MODE == 2) ? g_ao : A;

    const int lrow = t & 127;   // 32 consecutive rows per warp
    const int lkc  = t >> 7;    // 0/1

    const float* aptr = Ap + (size_t)(i0 + lrow) * K;
    const float* bptr = Bm + (size_t)(j0 + lrow) * K;

    float4 pa[2], pb[2];
#pragma unroll
    for (int it = 0; it < 2; ++it) {
        pa[it] = *(const float4*)(aptr + (lkc + 2 * it) * 4);
        pb[it] = *(const float4*)(bptr + (lkc + 2 * it) * 4);
    }

    u64 acc[8][4];
#pragma unroll
    for (int r = 0; r < 8; r++)
#pragma unroll
        for (int p = 0; p < 4; p++) acc[r][p] = 0ull;

    for (int k0 = 0; k0 < K; k0 += 16) {
        __syncthreads();
#pragma unroll
        for (int it = 0; it < 2; ++it) {
            int kk = (lkc + 2 * it) * 4;
            As[(kk + 0) * 128 + lrow] = pa[it].x;
            As[(kk + 1) * 128 + lrow] = pa[it].y;
            As[(kk + 2) * 128 + lrow] = pa[it].z;
            As[(kk + 3) * 128 + lrow] = pa[it].w;
            Bs[(kk + 0) * 128 + lrow] = pb[it].x;
            Bs[(kk + 1) * 128 + lrow] = pb[it].y;
            Bs[(kk + 2) * 128 + lrow] = pb[it].z;
            Bs[(kk + 3) * 128 + lrow] = pb[it].w;
        }
        __syncthreads();
        if (k0 + 16 < K) {
#pragma unroll
            for (int it = 0; it < 2; ++it) {
                pa[it] = *(const float4*)(aptr + k0 + 16 + (lkc + 2 * it) * 4);
                pb[it] = *(const float4*)(bptr + k0 + 16 + (lkc + 2 * it) * 4);
            }
        }
#pragma unroll
        for (int kk = 0; kk < 16; ++kk) {
            float4 a0 = *(const float4*)&As[kk * 128 + ty * 4];
            float4 a1 = *(const float4*)&As[kk * 128 + 64 + ty * 4];
            float4 b0 = *(const float4*)&Bs[kk * 128 + tx * 4];
            float4 b1 = *(const float4*)&Bs[kk * 128 + 64 + tx * 4];
            u64 bp0 = pk2(b0.x, b0.y), bp1 = pk2(b0.z, b0.w);
            u64 bp2 = pk2(b1.x, b1.y), bp3 = pk2(b1.z, b1.w);
            float av[8] = {a0.x, a0.y, a0.z, a0.w, a1.x, a1.y, a1.z, a1.w};
#pragma unroll
            for (int r = 0; r < 8; r++) {
                u64 ad = pk2(av[r], av[r]);
                acc[r][0] = fma2(ad, bp0, acc[r][0]);
                acc[r][1] = fma2(ad, bp1, acc[r][1]);
                acc[r][2] = fma2(ad, bp2, acc[r][2]);
                acc[r][3] = fma2(ad, bp3, acc[r][3]);
            }
        }
    }

#pragma unroll
    for (int r = 0; r < 8; r++) {
        int gi = i0 + (r >> 2) * 64 + ty * 4 + (r & 3);
#pragma unroll
        for (int p = 0; p < 4; p++) {
            float2 v = upk(acc[r][p]);
            int cb = j0 + (p >> 1) * 64 + tx * 4 + (p & 1) * 2;
            if (MODE == 1) {
                int b = gi >> 11, n = gi & 2047;
                size_t rp = (size_t)b * 131072 * Hh + (size_t)n * 64;
                int three0 = cb / 768, rem0 = cb - three0 * 768;
                g_qkv[(size_t)three0 * 6291456 + (size_t)(rem0 >> 6) * 131072 + rp + (rem0 & 63)] = v.x;
                int cb1 = cb + 1;
                int three1 = cb1 / 768, rem1 = cb1 - three1 * 768;
                g_qkv[(size_t)three1 * 6291456 + (size_t)(rem1 >> 6) * 131072 + rp + (rem1 & 63)] = v.y;
            } else {
                v.x += bias[cb]; v.y += bias[cb + 1];
                *(float2*)(C + (size_t)gi * N + cb) = v;
            }
        }
    }
}

// ---------------------------------------------------------------------------
// Fused flash attention (f32x2). CTA = (b,h) x 128-query tile, 256 threads.
// Q pre-scaled by 64*log2e; exp2-domain softmax; mask adds mk*(-1e6*log2e).
// ---------------------------------------------------------------------------
#define KSTR 128
#define VSTR 68
#define PSTR 132
#define ATTN_SMEM_FLOATS (2 * 64 * KSTR + 128 * VSTR + 128 * PSTR)
#define ATTN_SMEM_BYTES  (ATTN_SMEM_FLOATS * 4)

__global__ void __launch_bounds__(256) attn_kernel(const int* __restrict__ mask) {
    extern __shared__ float sm[];
    float* Qst = sm;                               // [64][128] transposed
    float* Kst = sm + 64 * KSTR;                   // [64][128] transposed
    float* Vs  = sm + 2 * 64 * KSTR;               // [128][64] natural (stride 68)
    float* Pst = sm + 2 * 64 * KSTR + 128 * VSTR;  // [128][128] natural (stride 132)

    const int t  = threadIdx.x;
    const int tx = t & 15, ty = t >> 4;
    const int bh = blockIdx.y;
    const int b  = bh / Hh;
    const int h  = bh - b * Hh;
    const int qbase = blockIdx.x * 128;

    const float* __restrict__ Qp = g_qkv + (size_t)bh * Nseq * Dd;
    const float* __restrict__ Kp = g_qkv + ((size_t)48 + bh) * Nseq * Dd;
    const float* __restrict__ Vp = g_qkv + ((size_t)96 + bh) * Nseq * Dd;

    const int lrow = t & 127;
    const int lsec = t >> 7;

    const float QS = 92.33248261972106f;    // 64 * log2(e)
    const float MC = -1442695.040888963f;   // -1e6 * log2(e)

#pragma unroll
    for (int it = 0; it < 8; ++it) {
        int dc = lsec + 2 * it;
        float4 v = *(const float4*)(Qp + (size_t)(qbase + lrow) * 64 + dc * 4);
        Qst[(dc * 4 + 0) * KSTR + lrow] = v.x * QS;
        Qst[(dc * 4 + 1) * KSTR + lrow] = v.y * QS;
        Qst[(dc * 4 + 2) * KSTR + lrow] = v.z * QS;
        Qst[(dc * 4 + 3) * KSTR + lrow] = v.w * QS;
    }

    u64 O[8][2];
    float m[8], l[8];
#pragma unroll
    for (int r = 0; r < 8; r++) { O[r][0] = 0; O[r][1] = 0; m[r] = -1e30f; l[r] = 0.f; }

    for (int kc = 0; kc < 16; ++kc) {
        const int kbase = kc * 128;
        __syncthreads();
#pragma unroll
        for (int it = 0; it < 8; ++it) {
            int dc = lsec + 2 * it;
            float4 kv = *(const float4*)(Kp + (size_t)(kbase + lrow) * 64 + dc * 4);
            Kst[(dc * 4 + 0) * KSTR + lrow] = kv.x;
            Kst[(dc * 4 + 1) * KSTR + lrow] = kv.y;
            Kst[(dc * 4 + 2) * KSTR + lrow] = kv.z;
            Kst[(dc * 4 + 3) * KSTR + lrow] = kv.w;
            *(float4*)&Vs[lrow * VSTR + dc * 4] =
                *(const float4*)(Vp + (size_t)(kbase + lrow) * 64 + dc * 4);
        }
        __syncthreads();

        // S = Q K^T over d=64
        u64 S[8][4];
#pragma unroll
        for (int r = 0; r < 8; r++)
#pragma unroll
            for (int p = 0; p < 4; p++) S[r][p] = 0;
#pragma unroll 8
        for (int d = 0; d < 64; ++d) {
            float4 q0 = *(const float4*)&Qst[d * KSTR + ty * 4];
            float4 q1 = *(const float4*)&Qst[d * KSTR + 64 + ty * 4];
            float4 k0 = *(const float4*)&Kst[d * KSTR + tx * 4];
            float4 k1 = *(const float4*)&Kst[d * KSTR + 64 + tx * 4];
            u64 bp0 = pk2(k0.x, k0.y), bp1 = pk2(k0.z, k0.w);
            u64 bp2 = pk2(k1.x, k1.y), bp3 = pk2(k1.z, k1.w);
            float qa[8] = {q0.x, q0.y, q0.z, q0.w, q1.x, q1.y, q1.z, q1.w};
#pragma unroll
            for (int r = 0; r < 8; r++) {
                u64 ad = pk2(qa[r], qa[r]);
                S[r][0] = fma2(ad, bp0, S[r][0]);
                S[r][1] = fma2(ad, bp1, S[r][1]);
                S[r][2] = fma2(ad, bp2, S[r][2]);
                S[r][3] = fma2(ad, bp3, S[r][3]);
            }
        }

        // mask + online softmax (exp2 domain)
#pragma unroll
        for (int r = 0; r < 8; r++) {
            int qrow = (r >> 2) * 64 + ty * 4 + (r & 3);
            float2 f0 = upk(S[r][0]), f1 = upk(S[r][1]);
            float2 f2 = upk(S[r][2]), f3 = upk(S[r][3]);
            float s[8] = {f0.x, f0.y, f1.x, f1.y, f2.x, f2.y, f3.x, f3.y};
            const int* mrow = mask + (size_t)(qbase + qrow) * 2048 + kbase;
            int4 m0 = *(const int4*)(mrow + tx * 4);
            int4 m1 = *(const int4*)(mrow + 64 + tx * 4);
            s[0] += (float)m0.x * MC; s[1] += (float)m0.y * MC;
            s[2] += (float)m0.z * MC; s[3] += (float)m0.w * MC;
            s[4] += (float)m1.x * MC; s[5] += (float)m1.y * MC;
            s[6] += (float)m1.z * MC; s[7] += (float)m1.w * MC;
            float rmax = s[0];
#pragma unroll
            for (int j = 1; j < 8; j++) rmax = fmaxf(rmax, s[j]);
#pragma unroll
            for (int off = 8; off; off >>= 1)
                rmax = fmaxf(rmax, __shfl_xor_sync(0xffffffffu, rmax, off));
            float mnew  = fmaxf(m[r], rmax);
            float alpha = ex2(m[r] - mnew);
            m[r] = mnew;
            float p[8], rs = 0.f;
#pragma unroll
            for (int j = 0; j < 8; j++) { p[j] = ex2(s[j] - mnew); rs += p[j]; }
#pragma unroll
            for (int off = 8; off; off >>= 1) rs += __shfl_xor_sync(0xffffffffu, rs, off);
            l[r] = l[r] * alpha + rs;
            u64 ap = pk2(alpha, alpha);
            O[r][0] = mul2(O[r][0], ap);
            O[r][1] = mul2(O[r][1], ap);
            float* prow = Pst + (size_t)qrow * PSTR;
            *(float2*)(prow + tx * 4)          = make_float2(p[0], p[1]);
            *(float2*)(prow + tx * 4 + 2)      = make_float2(p[2], p[3]);
            *(float2*)(prow + 64 + tx * 4)     = make_float2(p[4], p[5]);
            *(float2*)(prow + 64 + tx * 4 + 2) = make_float2(p[6], p[7]);
        }
        __syncthreads();

        // O += P V
#pragma unroll 4
        for (int c0 = 0; c0 < 128; c0 += 4) {
            u64 vp0[4], vp1[4];
#pragma unroll
            for (int j = 0; j < 4; j++) {
                float4 vf = *(const float4*)&Vs[(c0 + j) * VSTR + tx * 4];
                vp0[j] = pk2(vf.x, vf.y);
                vp1[j] = pk2(vf.z, vf.w);
            }
#pragma unroll
            for (int r = 0; r < 8; r++) {
                int qrow = (r >> 2) * 64 + ty * 4 + (r & 3);
                float4 pf = *(const float4*)&Pst[(size_t)qrow * PSTR + c0];
                float pa[4] = {pf.x, pf.y, pf.z, pf.w};
#pragma unroll
                for (int j = 0; j < 4; j++) {
                    u64 ad = pk2(pa[j], pa[j]);
                    O[r][0] = fma2(ad, vp0[j], O[r][0]);
                    O[r][1] = fma2(ad, vp1[j], O[r][1]);
                }
            }
        }
    }

    // write g_ao [B][N][C] at (b, qbase+qrow, h*64 + tx*4)
#pragma unroll
    for (int r = 0; r < 8; r++) {
        int qrow = (r >> 2) * 64 + ty * 4 + (r & 3);
        float inv = 1.f / l[r];
        float2 o0 = upk(O[r][0]), o1 = upk(O[r][1]);
        float4 o = make_float4(o0.x * inv, o0.y * inv, o1.x * inv, o1.y * inv);
        *(float4*)(g_ao + (size_t)(b * Nseq + qbase + qrow) * Cdim + h * 64 + tx * 4) = o;
    }
}

// ---------------------------------------------------------------------------
extern "C" void kernel_launch(void* const* d_in, const int* in_sizes, int n_in,
                              void* d_out, int out_size) {
    const float* x      = (const float*)d_in[0];
    const int*   mask   = (const int*)  d_in[1];
    const float* qkv_w  = (const float*)d_in[2];
    const float* proj_w = (const float*)d_in[3];
    const float* proj_b = (const float*)d_in[4];
    float*       out    = (float*)d_out;

    cudaFuncSetAttribute(attn_kernel,
                         cudaFuncAttributeMaxDynamicSharedMemorySize, ATTN_SMEM_BYTES);

    const int M = Bc * Nseq;  // 8192
    gemm_nt<1><<<dim3((3 * Cdim) / 128, M / 128), 256>>>(x, qkv_w, nullptr, nullptr,
                                                         M, 3 * Cdim, Cdim);
    attn_kernel<<<dim3(Nseq / 128, Bc * Hh), 256, ATTN_SMEM_BYTES>>>(mask);
    gemm_nt<2><<<dim3(Cdim / 128, M / 128), 256>>>(nullptr, proj_w, proj_b, out,
                                                   M, Cdim, Cdim);
}

// round 6
// speedup vs baseline: 1.4163x; 1.1706x over previous
// v5: identical to round-4 HMMA design; resubmitted after container-level failure
// (audit found no defect; testing infra-flake hypothesis).
#include <cuda_runtime.h>
#include <cuda_bf16.h>
#include <cstdint>

#define Bc   4
#define Nseq 2048
#define Cdim 768
#define Hh   12
#define Dd   64

using u64 = unsigned long long;
using u32 = unsigned int;

// ---------------- f32x2 helpers (attention) ----------------
__device__ __forceinline__ u64 fma2(u64 a, u64 b, u64 c) {
    u64 d; asm("fma.rn.f32x2 %0,%1,%2,%3;" : "=l"(d) : "l"(a), "l"(b), "l"(c)); return d;
}
__device__ __forceinline__ u64 mul2(u64 a, u64 b) {
    u64 d; asm("mul.rn.f32x2 %0,%1,%2;" : "=l"(d) : "l"(a), "l"(b)); return d;
}
__device__ __forceinline__ u64 pk2(float x, float y) {
    u64 r; asm("mov.b64 %0,{%1,%2};" : "=l"(r) : "f"(x), "f"(y)); return r;
}
__device__ __forceinline__ float2 upk(u64 v) {
    float2 f; asm("mov.b64 {%0,%1},%2;" : "=f"(f.x), "=f"(f.y) : "l"(v)); return f;
}
__device__ __forceinline__ float ex2(float x) {
    float y; asm("ex2.approx.f32 %0,%1;" : "=f"(y) : "f"(x)); return y;
}

// ---------------- mma.sync helpers (sm_80+ baseline) ----------------------
__device__ __forceinline__ u32 smem_u32(const void* p) {
    u32 a; asm("{ .reg .u64 t; cvta.to.shared.u64 t, %1; cvt.u32.u64 %0, t; }" : "=r"(a) : "l"(p));
    return a;
}
__device__ __forceinline__ void ldm4(u32& r0, u32& r1, u32& r2, u32& r3, u32 addr) {
    asm volatile("ldmatrix.sync.aligned.m8n8.x4.shared.b16 {%0,%1,%2,%3},[%4];"
        : "=r"(r0), "=r"(r1), "=r"(r2), "=r"(r3) : "r"(addr));
}
__device__ __forceinline__ void mma16816(float* c, u32 a0, u32 a1, u32 a2, u32 a3,
                                         u32 b0, u32 b1) {
    asm volatile("mma.sync.aligned.m16n8k16.row.col.f32.bf16.bf16.f32 "
        "{%0,%1,%2,%3},{%4,%5,%6,%7},{%8,%9},{%0,%1,%2,%3};"
        : "+f"(c[0]), "+f"(c[1]), "+f"(c[2]), "+f"(c[3])
        : "r"(a0), "r"(a1), "r"(a2), "r"(a3), "r"(b0), "r"(b1));
}

// Scratch
__device__ float g_qkv[(size_t)3 * Bc * Hh * Nseq * Dd];   // [3][B][H][N][D]
__device__ float g_ao[(size_t)Bc * Nseq * Cdim];           // [B][N][C]

// ===========================================================================
// HMMA split-bf16 GEMM NT: C[M,N] = A[M,768] * B[N,768]^T, fp32-equivalent.
// Per 64-wide k-chunk: A_hi/A_lo/B_hi/B_lo bf16 tiles (SW128-swizzled),
// 3 passes: Ahi*Bhi + Ahi*Blo + Alo*Bhi (m16n8k16, fp32 acc).
// CTA 128x128, 8 warps (warp tile 64x32), 2-stage smem (128 KB).
// ===========================================================================
#define TILE_B 16384
#define STG_B  (4 * TILE_B)
#define GEMM_SMEM (2 * STG_B)

__device__ __forceinline__ void fill_pair(const float* __restrict__ src, char* hi,
                                          char* lo, int kbase, int t) {
#pragma unroll
    for (int it = 0; it < 8; ++it) {
        int f4  = t + it * 256;        // 0..2047
        int row = f4 >> 4;             // 0..127
        int c4  = (f4 & 15) << 2;      // 0..60
        float4 v = *(const float4*)(src + (size_t)row * 768 + kbase + c4);
        __nv_bfloat16 h0 = __float2bfloat16(v.x), h1 = __float2bfloat16(v.y);
        __nv_bfloat16 h2 = __float2bfloat16(v.z), h3 = __float2bfloat16(v.w);
        __nv_bfloat16 l0 = __float2bfloat16(v.x - __bfloat162float(h0));
        __nv_bfloat16 l1 = __float2bfloat16(v.y - __bfloat162float(h1));
        __nv_bfloat16 l2 = __float2bfloat16(v.z - __bfloat162float(h2));
        __nv_bfloat16 l3 = __float2bfloat16(v.w - __bfloat162float(h3));
        u32 off = (u32)(row * 128 + c4 * 2);
        u32 sw  = off ^ ((off >> 3) & 0x70);
        __nv_bfloat162 ph0; ph0.x = h0; ph0.y = h1;
        __nv_bfloat162 ph1; ph1.x = h2; ph1.y = h3;
        __nv_bfloat162 pl0; pl0.x = l0; pl0.y = l1;
        __nv_bfloat162 pl1; pl1.x = l2; pl1.y = l3;
        uint2 uh; uh.x = *(u32*)&ph0; uh.y = *(u32*)&ph1;
        uint2 ul; ul.x = *(u32*)&pl0; ul.y = *(u32*)&pl1;
        *(uint2*)(hi + sw) = uh;
        *(uint2*)(lo + sw) = ul;
    }
}

template<int MODE>
__global__ void __launch_bounds__(256) gemm_mma(const float* __restrict__ A_,
                                                const float* __restrict__ Bw,
                                                const float* __restrict__ bias,
                                                float* __restrict__ C, int Nn) {
    extern __shared__ __align__(1024) char smem[];
    const u32 sb   = smem_u32(smem);
    const int t    = threadIdx.x, lane = t & 31, wid = t >> 5;
    const int i0   = blockIdx.y * 128, j0 = blockIdx.x * 128;
    const float* __restrict__ Arow = ((MODE == 2) ? g_ao : A_) + (size_t)i0 * 768;
    const float* __restrict__ Brow = Bw + (size_t)j0 * 768;

    const int m0  = (wid >> 2) * 64;
    const int n0  = (wid & 3) * 32;
    const int lr  = lane & 15;
    const int chi = lane >> 4;
    const u32 xorv = (u32)((lane & 7) << 4);

    float acc[4][4][4];
#pragma unroll
    for (int i = 0; i < 4; i++)
#pragma unroll
        for (int j = 0; j < 4; j++)
#pragma unroll
            for (int k = 0; k < 4; k++) acc[i][j][k] = 0.f;

    fill_pair(Arow, smem + 0,          smem + TILE_B,     0, t);
    fill_pair(Brow, smem + 2 * TILE_B, smem + 3 * TILE_B, 0, t);
    __syncthreads();

    for (int kc = 0; kc < 12; ++kc) {
        const int st = kc & 1;
        if (kc + 1 < 12) {
            char* nb = smem + (st ^ 1) * STG_B;
            fill_pair(Arow, nb,              nb + TILE_B,     (kc + 1) * 64, t);
            fill_pair(Brow, nb + 2 * TILE_B, nb + 3 * TILE_B, (kc + 1) * 64, t);
        }
        __syncthreads();

        const u32 base = sb + st * STG_B;
#pragma unroll
        for (int s = 0; s < 4; ++s) {
            const u32 colterm = ((u32)((2 * s + chi) << 4)) ^ xorv;
            u32 ah[4][4], al[4][4];
#pragma unroll
            for (int i = 0; i < 4; i++) {
                u32 ra = base + (u32)((m0 + i * 16 + lr) * 128) + colterm;
                ldm4(ah[i][0], ah[i][1], ah[i][2], ah[i][3], ra);
                ldm4(al[i][0], al[i][1], al[i][2], al[i][3], ra + TILE_B);
            }
            u32 bh[8], bl[8];
#pragma unroll
            for (int j = 0; j < 2; j++) {
                u32 rb = base + 2 * TILE_B + (u32)((n0 + j * 16 + lr) * 128) + colterm;
                ldm4(bh[j * 4 + 0], bh[j * 4 + 1], bh[j * 4 + 2], bh[j * 4 + 3], rb);
                ldm4(bl[j * 4 + 0], bl[j * 4 + 1], bl[j * 4 + 2], bl[j * 4 + 3], rb + TILE_B);
            }
#pragma unroll
            for (int i = 0; i < 4; i++)
#pragma unroll
                for (int jj = 0; jj < 4; jj++) {
                    int j4 = (jj >> 1) * 4 + (jj & 1);
                    mma16816(acc[i][jj], ah[i][0], ah[i][1], ah[i][2], ah[i][3],
                             bh[j4], bh[j4 + 2]);
                    mma16816(acc[i][jj], ah[i][0], ah[i][1], ah[i][2], ah[i][3],
                             bl[j4], bl[j4 + 2]);
                    mma16816(acc[i][jj], al[i][0], al[i][1], al[i][2], al[i][3],
                             bh[j4], bh[j4 + 2]);
                }
        }
        __syncthreads();
    }

#pragma unroll
    for (int i = 0; i < 4; i++) {
        int r0 = m0 + i * 16 + (lane >> 2);
#pragma unroll
        for (int jj = 0; jj < 4; jj++) {
            int col = n0 + jj * 8 + 2 * (lane & 3);
#pragma unroll
            for (int half = 0; half < 2; half++) {
                int gi = i0 + r0 + half * 8;
                int gj = j0 + col;
                float2 v;
                v.x = acc[i][jj][half * 2 + 0];
                v.y = acc[i][jj][half * 2 + 1];
                if (MODE == 1) {
                    int b = gi >> 11, n = gi & 2047;
                    int three = gj / 768, rem = gj - three * 768;
                    size_t idx = (size_t)three * 6291456 + (size_t)b * 1572864 +
                                 (size_t)(rem >> 6) * 131072 + (size_t)n * 64 + (rem & 63);
                    *(float2*)(g_qkv + idx) = v;
                } else {
                    v.x += bias[gj];
                    v.y += bias[gj + 1];
                    *(float2*)(C + (size_t)gi * Nn + gj) = v;
                }
            }
        }
    }
}

// ===========================================================================
// Fused flash attention (f32x2) — round-3 passing version, unchanged.
// ===========================================================================
#define KSTR 128
#define VSTR 68
#define PSTR 132
#define ATTN_SMEM_FLOATS (2 * 64 * KSTR + 128 * VSTR + 128 * PSTR)
#define ATTN_SMEM_BYTES  (ATTN_SMEM_FLOATS * 4)

__global__ void __launch_bounds__(256) attn_kernel(const int* __restrict__ mask) {
    extern __shared__ float sm[];
    float* Qst = sm;
    float* Kst = sm + 64 * KSTR;
    float* Vs  = sm + 2 * 64 * KSTR;
    float* Pst = sm + 2 * 64 * KSTR + 128 * VSTR;

    const int t  = threadIdx.x;
    const int tx = t & 15, ty = t >> 4;
    const int bh = blockIdx.y;
    const int b  = bh / Hh;
    const int h  = bh - b * Hh;
    const int qbase = blockIdx.x * 128;

    const float* __restrict__ Qp = g_qkv + (size_t)bh * Nseq * Dd;
    const float* __restrict__ Kp = g_qkv + ((size_t)48 + bh) * Nseq * Dd;
    const float* __restrict__ Vp = g_qkv + ((size_t)96 + bh) * Nseq * Dd;

    const int lrow = t & 127;
    const int lsec = t >> 7;

    const float QS = 92.33248261972106f;    // 64 * log2(e)
    const float MC = -1442695.040888963f;   // -1e6 * log2(e)

#pragma unroll
    for (int it = 0; it < 8; ++it) {
        int dc = lsec + 2 * it;
        float4 v = *(const float4*)(Qp + (size_t)(qbase + lrow) * 64 + dc * 4);
        Qst[(dc * 4 + 0) * KSTR + lrow] = v.x * QS;
        Qst[(dc * 4 + 1) * KSTR + lrow] = v.y * QS;
        Qst[(dc * 4 + 2) * KSTR + lrow] = v.z * QS;
        Qst[(dc * 4 + 3) * KSTR + lrow] = v.w * QS;
    }

    u64 O[8][2];
    float m[8], l[8];
#pragma unroll
    for (int r = 0; r < 8; r++) { O[r][0] = 0; O[r][1] = 0; m[r] = -1e30f; l[r] = 0.f; }

    for (int kc = 0; kc < 16; ++kc) {
        const int kbase = kc * 128;
        __syncthreads();
#pragma unroll
        for (int it = 0; it < 8; ++it) {
            int dc = lsec + 2 * it;
            float4 kv = *(const float4*)(Kp + (size_t)(kbase + lrow) * 64 + dc * 4);
            Kst[(dc * 4 + 0) * KSTR + lrow] = kv.x;
            Kst[(dc * 4 + 1) * KSTR + lrow] = kv.y;
            Kst[(dc * 4 + 2) * KSTR + lrow] = kv.z;
            Kst[(dc * 4 + 3) * KSTR + lrow] = kv.w;
            *(float4*)&Vs[lrow * VSTR + dc * 4] =
                *(const float4*)(Vp + (size_t)(kbase + lrow) * 64 + dc * 4);
        }
        __syncthreads();

        u64 S[8][4];
#pragma unroll
        for (int r = 0; r < 8; r++)
#pragma unroll
            for (int p = 0; p < 4; p++) S[r][p] = 0;
#pragma unroll 8
        for (int d = 0; d < 64; ++d) {
            float4 q0 = *(const float4*)&Qst[d * KSTR + ty * 4];
            float4 q1 = *(const float4*)&Qst[d * KSTR + 64 + ty * 4];
            float4 k0 = *(const float4*)&Kst[d * KSTR + tx * 4];
            float4 k1 = *(const float4*)&Kst[d * KSTR + 64 + tx * 4];
            u64 bp0 = pk2(k0.x, k0.y), bp1 = pk2(k0.z, k0.w);
            u64 bp2 = pk2(k1.x, k1.y), bp3 = pk2(k1.z, k1.w);
            float qa[8] = {q0.x, q0.y, q0.z, q0.w, q1.x, q1.y, q1.z, q1.w};
#pragma unroll
            for (int r = 0; r < 8; r++) {
                u64 ad = pk2(qa[r], qa[r]);
                S[r][0] = fma2(ad, bp0, S[r][0]);
                S[r][1] = fma2(ad, bp1, S[r][1]);
                S[r][2] = fma2(ad, bp2, S[r][2]);
                S[r][3] = fma2(ad, bp3, S[r][3]);
            }
        }

#pragma unroll
        for (int r = 0; r < 8; r++) {
            int qrow = (r >> 2) * 64 + ty * 4 + (r & 3);
            float2 f0 = upk(S[r][0]), f1 = upk(S[r][1]);
            float2 f2 = upk(S[r][2]), f3 = upk(S[r][3]);
            float s[8] = {f0.x, f0.y, f1.x, f1.y, f2.x, f2.y, f3.x, f3.y};
            const int* mrow = mask + (size_t)(qbase + qrow) * 2048 + kbase;
            int4 m0 = *(const int4*)(mrow + tx * 4);
            int4 m1 = *(const int4*)(mrow + 64 + tx * 4);
            s[0] += (float)m0.x * MC; s[1] += (float)m0.y * MC;
            s[2] += (float)m0.z * MC; s[3] += (float)m0.w * MC;
            s[4] += (float)m1.x * MC; s[5] += (float)m1.y * MC;
            s[6] += (float)m1.z * MC; s[7] += (float)m1.w * MC;
            float rmax = s[0];
#pragma unroll
            for (int j = 1; j < 8; j++) rmax = fmaxf(rmax, s[j]);
#pragma unroll
            for (int off = 8; off; off >>= 1)
                rmax = fmaxf(rmax, __shfl_xor_sync(0xffffffffu, rmax, off));
            float mnew  = fmaxf(m[r], rmax);
            float alpha = ex2(m[r] - mnew);
            m[r] = mnew;
            float p[8], rs = 0.f;
#pragma unroll
            for (int j = 0; j < 8; j++) { p[j] = ex2(s[j] - mnew); rs += p[j]; }
#pragma unroll
            for (int off = 8; off; off >>= 1) rs += __shfl_xor_sync(0xffffffffu, rs, off);
            l[r] = l[r] * alpha + rs;
            u64 ap = pk2(alpha, alpha);
            O[r][0] = mul2(O[r][0], ap);
            O[r][1] = mul2(O[r][1], ap);
            float* prow = Pst + (size_t)qrow * PSTR;
            *(float2*)(prow + tx * 4)          = make_float2(p[0], p[1]);
            *(float2*)(prow + tx * 4 + 2)      = make_float2(p[2], p[3]);
            *(float2*)(prow + 64 + tx * 4)     = make_float2(p[4], p[5]);
            *(float2*)(prow + 64 + tx * 4 + 2) = make_float2(p[6], p[7]);
        }
        __syncthreads();

#pragma unroll 4
        for (int c0 = 0; c0 < 128; c0 += 4) {
            u64 vp0[4], vp1[4];
#pragma unroll
            for (int j = 0; j < 4; j++) {
                float4 vf = *(const float4*)&Vs[(c0 + j) * VSTR + tx * 4];
                vp0[j] = pk2(vf.x, vf.y);
                vp1[j] = pk2(vf.z, vf.w);
            }
#pragma unroll
            for (int r = 0; r < 8; r++) {
                int qrow = (r >> 2) * 64 + ty * 4 + (r & 3);
                float4 pf = *(const float4*)&Pst[(size_t)qrow * PSTR + c0];
                float pa[4] = {pf.x, pf.y, pf.z, pf.w};
#pragma unroll
                for (int j = 0; j < 4; j++) {
                    u64 ad = pk2(pa[j], pa[j]);
                    O[r][0] = fma2(ad, vp0[j], O[r][0]);
                    O[r][1] = fma2(ad, vp1[j], O[r][1]);
                }
            }
        }
    }

#pragma unroll
    for (int r = 0; r < 8; r++) {
        int qrow = (r >> 2) * 64 + ty * 4 + (r & 3);
        float inv = 1.f / l[r];
        float2 o0 = upk(O[r][0]), o1 = upk(O[r][1]);
        float4 o = make_float4(o0.x * inv, o0.y * inv, o1.x * inv, o1.y * inv);
        *(float4*)(g_ao + (size_t)(b * Nseq + qbase + qrow) * Cdim + h * 64 + tx * 4) = o;
    }
}

// ---------------------------------------------------------------------------
extern "C" void kernel_launch(void* const* d_in, const int* in_sizes, int n_in,
                              void* d_out, int out_size) {
    const float* x      = (const float*)d_in[0];
    const int*   mask   = (const int*)  d_in[1];
    const float* qkv_w  = (const float*)d_in[2];
    const float* proj_w = (const float*)d_in[3];
    const float* proj_b = (const float*)d_in[4];
    float*       out    = (float*)d_out;

    cudaFuncSetAttribute(attn_kernel,
                         cudaFuncAttributeMaxDynamicSharedMemorySize, ATTN_SMEM_BYTES);
    cudaFuncSetAttribute(gemm_mma<1>,
                         cudaFuncAttributeMaxDynamicSharedMemorySize, GEMM_SMEM);
    cudaFuncSetAttribute(gemm_mma<2>,
                         cudaFuncAttributeMaxDynamicSharedMemorySize, GEMM_SMEM);

    gemm_mma<1><<<dim3(2304 / 128, 8192 / 128), 256, GEMM_SMEM>>>(x, qkv_w, nullptr,
                                                                  nullptr, 2304);
    attn_kernel<<<dim3(Nseq / 128, Bc * Hh), 256, ATTN_SMEM_BYTES>>>(mask);
    gemm_mma<2><<<dim3(768 / 128, 8192 / 128), 256, GEMM_SMEM>>>(nullptr, proj_w, proj_b,
                                                                 out, 768);
}

// round 7
// speedup vs baseline: 1.9803x; 1.3983x over previous
// v7: attention on HMMA (split-bf16, 3-pass) + FFMA-based exp2 (MUFU bound removed).
// GEMMs unchanged from round 6 (passing, 394us/130us).
#include <cuda_runtime.h>
#include <cuda_bf16.h>
#include <cstdint>

#define Bc   4
#define Nseq 2048
#define Cdim 768
#define Hh   12
#define Dd   64

using u64 = unsigned long long;
using u32 = unsigned int;

__device__ __forceinline__ float ex2(float x) {
    float y; asm("ex2.approx.f32 %0,%1;" : "=f"(y) : "f"(x)); return y;
}
__device__ __forceinline__ u32 smem_u32(const void* p) {
    u32 a; asm("{ .reg .u64 t; cvta.to.shared.u64 t, %1; cvt.u32.u64 %0, t; }" : "=r"(a) : "l"(p));
    return a;
}
__device__ __forceinline__ void ldm4(u32& r0, u32& r1, u32& r2, u32& r3, u32 addr) {
    asm volatile("ldmatrix.sync.aligned.m8n8.x4.shared.b16 {%0,%1,%2,%3},[%4];"
        : "=r"(r0), "=r"(r1), "=r"(r2), "=r"(r3) : "r"(addr));
}
__device__ __forceinline__ void mma16816(float* c, u32 a0, u32 a1, u32 a2, u32 a3,
                                         u32 b0, u32 b1) {
    asm volatile("mma.sync.aligned.m16n8k16.row.col.f32.bf16.bf16.f32 "
        "{%0,%1,%2,%3},{%4,%5,%6,%7},{%8,%9},{%0,%1,%2,%3};"
        : "+f"(c[0]), "+f"(c[1]), "+f"(c[2]), "+f"(c[3])
        : "r"(a0), "r"(a1), "r"(a2), "r"(a3), "r"(b0), "r"(b1));
}
// pack two fp32 -> bf16x2 {lo, hi}
__device__ __forceinline__ u32 pkbf(float lo, float hi) {
    u32 r; asm("cvt.rn.bf16x2.f32 %0,%1,%2;" : "=r"(r) : "f"(hi), "f"(lo)); return r;
}
// split (x,y) into bf16x2 hi + bf16x2 lo (residual)
__device__ __forceinline__ void split2(float x, float y, u32& hi, u32& lo) {
    hi = pkbf(x, y);
    float hx = __int_as_float(hi << 16);
    float hy = __int_as_float(hi & 0xFFFF0000u);
    lo = pkbf(x - hx, y - hy);
}
// FFMA-only exp2 for x <= 0 (clamped at -126); rel err ~4e-5
__device__ __forceinline__ float exp2p(float x) {
    x = fmaxf(x, -126.0f);
    float t = x + 12582912.0f;                       // 1.5*2^23 round-to-nearest
    int  k  = __float_as_int(t) - 0x4B400000;        // round(x)
    float xf = x - (t - 12582912.0f);                // [-0.5, 0.5]
    float p = 0.0096180f;
    p = p * xf + 0.0555041f;
    p = p * xf + 0.2402265f;
    p = p * xf + 0.6931472f;
    p = p * xf + 1.0f;
    return p * __int_as_float((k + 127) << 23);
}

// Scratch
__device__ float g_qkv[(size_t)3 * Bc * Hh * Nseq * Dd];   // [3][B][H][N][D]
__device__ float g_ao[(size_t)Bc * Nseq * Cdim];           // [B][N][C]

// ===========================================================================
// HMMA split-bf16 GEMM NT (unchanged from round 6)
// ===========================================================================
#define TILE_B 16384
#define STG_B  (4 * TILE_B)
#define GEMM_SMEM (2 * STG_B)

__device__ __forceinline__ void fill_pair(const float* __restrict__ src, char* hi,
                                          char* lo, int kbase, int t) {
#pragma unroll
    for (int it = 0; it < 8; ++it) {
        int f4  = t + it * 256;
        int row = f4 >> 4;
        int c4  = (f4 & 15) << 2;
        float4 v = *(const float4*)(src + (size_t)row * 768 + kbase + c4);
        u32 h01, l01, h23, l23;
        split2(v.x, v.y, h01, l01);
        split2(v.z, v.w, h23, l23);
        u32 off = (u32)(row * 128 + c4 * 2);
        u32 sw  = off ^ ((off >> 3) & 0x70);
        uint2 uh; uh.x = h01; uh.y = h23;
        uint2 ul; ul.x = l01; ul.y = l23;
        *(uint2*)(hi + sw) = uh;
        *(uint2*)(lo + sw) = ul;
    }
}

template<int MODE>
__global__ void __launch_bounds__(256) gemm_mma(const float* __restrict__ A_,
                                                const float* __restrict__ Bw,
                                                const float* __restrict__ bias,
                                                float* __restrict__ C, int Nn) {
    extern __shared__ __align__(1024) char smem[];
    const u32 sb   = smem_u32(smem);
    const int t    = threadIdx.x, lane = t & 31, wid = t >> 5;
    const int i0   = blockIdx.y * 128, j0 = blockIdx.x * 128;
    const float* __restrict__ Arow = ((MODE == 2) ? g_ao : A_) + (size_t)i0 * 768;
    const float* __restrict__ Brow = Bw + (size_t)j0 * 768;

    const int m0  = (wid >> 2) * 64;
    const int n0  = (wid & 3) * 32;
    const int lr  = lane & 15;
    const int chi = lane >> 4;
    const u32 xorv = (u32)((lane & 7) << 4);

    float acc[4][4][4];
#pragma unroll
    for (int i = 0; i < 4; i++)
#pragma unroll
        for (int j = 0; j < 4; j++)
#pragma unroll
            for (int k = 0; k < 4; k++) acc[i][j][k] = 0.f;

    fill_pair(Arow, smem + 0,          smem + TILE_B,     0, t);
    fill_pair(Brow, smem + 2 * TILE_B, smem + 3 * TILE_B, 0, t);
    __syncthreads();

    for (int kc = 0; kc < 12; ++kc) {
        const int st = kc & 1;
        if (kc + 1 < 12) {
            char* nb = smem + (st ^ 1) * STG_B;
            fill_pair(Arow, nb,              nb + TILE_B,     (kc + 1) * 64, t);
            fill_pair(Brow, nb + 2 * TILE_B, nb + 3 * TILE_B, (kc + 1) * 64, t);
        }
        __syncthreads();

        const u32 base = sb + st * STG_B;
#pragma unroll
        for (int s = 0; s < 4; ++s) {
            const u32 colterm = ((u32)((2 * s + chi) << 4)) ^ xorv;
            u32 ah[4][4], al[4][4];
#pragma unroll
            for (int i = 0; i < 4; i++) {
                u32 ra = base + (u32)((m0 + i * 16 + lr) * 128) + colterm;
                ldm4(ah[i][0], ah[i][1], ah[i][2], ah[i][3], ra);
                ldm4(al[i][0], al[i][1], al[i][2], al[i][3], ra + TILE_B);
            }
            u32 bh[8], bl[8];
#pragma unroll
            for (int j = 0; j < 2; j++) {
                u32 rb = base + 2 * TILE_B + (u32)((n0 + j * 16 + lr) * 128) + colterm;
                ldm4(bh[j * 4 + 0], bh[j * 4 + 1], bh[j * 4 + 2], bh[j * 4 + 3], rb);
                ldm4(bl[j * 4 + 0], bl[j * 4 + 1], bl[j * 4 + 2], bl[j * 4 + 3], rb + TILE_B);
            }
#pragma unroll
            for (int i = 0; i < 4; i++)
#pragma unroll
                for (int jj = 0; jj < 4; jj++) {
                    int j4 = (jj >> 1) * 4 + (jj & 1);
                    mma16816(acc[i][jj], ah[i][0], ah[i][1], ah[i][2], ah[i][3],
                             bh[j4], bh[j4 + 2]);
                    mma16816(acc[i][jj], ah[i][0], ah[i][1], ah[i][2], ah[i][3],
                             bl[j4], bl[j4 + 2]);
                    mma16816(acc[i][jj], al[i][0], al[i][1], al[i][2], al[i][3],
                             bh[j4], bh[j4 + 2]);
                }
        }
        __syncthreads();
    }

#pragma unroll
    for (int i = 0; i < 4; i++) {
        int r0 = m0 + i * 16 + (lane >> 2);
#pragma unroll
        for (int jj = 0; jj < 4; jj++) {
            int col = n0 + jj * 8 + 2 * (lane & 3);
#pragma unroll
            for (int half = 0; half < 2; half++) {
                int gi = i0 + r0 + half * 8;
                int gj = j0 + col;
                float2 v;
                v.x = acc[i][jj][half * 2 + 0];
                v.y = acc[i][jj][half * 2 + 1];
                if (MODE == 1) {
                    int b = gi >> 11, n = gi & 2047;
                    int three = gj / 768, rem = gj - three * 768;
                    size_t idx = (size_t)three * 6291456 + (size_t)b * 1572864 +
                                 (size_t)(rem >> 6) * 131072 + (size_t)n * 64 + (rem & 63);
                    *(float2*)(g_qkv + idx) = v;
                } else {
                    v.x += bias[gj];
                    v.y += bias[gj + 1];
                    *(float2*)(C + (size_t)gi * Nn + gj) = v;
                }
            }
        }
    }
}

// ===========================================================================
// HMMA flash attention. CTA = (b,h) x 128-q tile; 8 warps, warp = 16 q-rows.
// S: m16n128k64 split-bf16 3-pass. P->A-frags in-register. PV: 3-pass.
// exp2 via FFMA poly (no MUFU per score).
// ===========================================================================
#define AQHI 0
#define AQLO 16384
#define AKHI 32768
#define AKLO 49152
#define AVHI 65536
#define AVLO 81920
#define ATTN_SMEM 98304

// fill [128][64] fp32 (row stride 64) -> hi/lo bf16 tiles, 128B rows, SW128
__device__ __forceinline__ void fill_qk(const float* __restrict__ src, char* hi,
                                        char* lo, float scale, int t) {
#pragma unroll
    for (int it = 0; it < 8; ++it) {
        int slot = t + it * 256;
        int row  = slot >> 4;
        int c4   = (slot & 15) << 2;
        float4 v = *(const float4*)(src + (size_t)row * 64 + c4);
        u32 h01, l01, h23, l23;
        split2(v.x * scale, v.y * scale, h01, l01);
        split2(v.z * scale, v.w * scale, h23, l23);
        u32 off = (u32)(row * 128 + c4 * 2);
        u32 sw  = off ^ ((off >> 3) & 0x70);
        uint2 uh; uh.x = h01; uh.y = h23;
        uint2 ul; ul.x = l01; ul.y = l23;
        *(uint2*)(hi + sw) = uh;
        *(uint2*)(lo + sw) = ul;
    }
}

// fill V [128][64] fp32 -> transposed Vt [64][128] bf16 hi/lo, rows 256B,
// swizzle: byte ^ ((d&7)<<4)
__device__ __forceinline__ void fill_vt(const float* __restrict__ src, char* hi,
                                        char* lo, int t) {
#pragma unroll
    for (int it = 0; it < 8; ++it) {
        int slot = t + it * 256;
        int kq   = slot >> 4;
        int d4   = (slot & 15) << 2;
        float4 v = *(const float4*)(src + (size_t)kq * 64 + d4);
        float vv[4] = {v.x, v.y, v.z, v.w};
#pragma unroll
        for (int i = 0; i < 4; ++i) {
            int d = d4 + i;
            u32 byte = (u32)(d * 256 + kq * 2);
            u32 sw   = byte ^ (u32)((d & 7) << 4);
            __nv_bfloat16 bh = __float2bfloat16(vv[i]);
            __nv_bfloat16 bl = __float2bfloat16(vv[i] - __bfloat162float(bh));
            *(__nv_bfloat16*)(hi + sw) = bh;
            *(__nv_bfloat16*)(lo + sw) = bl;
        }
    }
}

__global__ void __launch_bounds__(256) attn_mma(const int* __restrict__ mask) {
    extern __shared__ __align__(1024) char smem[];
    const u32 sb = smem_u32(smem);
    const int t  = threadIdx.x, lane = t & 31, w = t >> 5;
    const int g  = lane >> 2, tg = lane & 3;
    const int lr = lane & 15, chi = lane >> 4;
    const int bh = blockIdx.y;
    const int b  = bh / Hh, h = bh - b * Hh;
    const int qbase = blockIdx.x * 128;
    const int qw = w * 16;

    const float* __restrict__ Qp = g_qkv + (size_t)bh * Nseq * Dd;
    const float* __restrict__ Kp = g_qkv + ((size_t)48 + bh) * Nseq * Dd;
    const float* __restrict__ Vp = g_qkv + ((size_t)96 + bh) * Nseq * Dd;

    const float QS = 92.33248261972106f;    // 64 * log2(e)
    const float MC = -1442695.040888963f;   // -1e6 * log2(e)

    fill_qk(Qp + (size_t)qbase * 64, smem + AQHI, smem + AQLO, QS, t);

    float O[8][4];
#pragma unroll
    for (int i = 0; i < 8; i++)
#pragma unroll
        for (int j = 0; j < 4; j++) O[i][j] = 0.f;
    float mm0 = -1e30f, mm1 = -1e30f, ll0 = 0.f, ll1 = 0.f;

    const int mrow0 = (qbase + qw + g) * 2048;
    const int mrow1 = mrow0 + 8 * 2048;

    for (int kc = 0; kc < 16; ++kc) {
        const int kbase = kc * 128;
        __syncthreads();
        fill_qk(Kp + (size_t)kbase * 64, smem + AKHI, smem + AKLO, 1.0f, t);
        fill_vt(Vp + (size_t)kbase * 64, smem + AVHI, smem + AVLO, t);
        __syncthreads();

        // ---- S = Q K^T (3-pass split) ----
        float S[16][4];
#pragma unroll
        for (int i = 0; i < 16; i++)
#pragma unroll
            for (int j = 0; j < 4; j++) S[i][j] = 0.f;

#pragma unroll
        for (int pass = 0; pass < 3; ++pass) {
            const u32 abase = sb + (pass == 2 ? AQLO : AQHI);
            const u32 bbase = sb + (pass == 1 ? AKLO : AKHI);
            u32 a[4][4];
#pragma unroll
            for (int ks = 0; ks < 4; ++ks) {
                int row = qw + lr;
                u32 cb = (u32)((ks * 32 + chi * 16) ^ ((row & 7) << 4));
                ldm4(a[ks][0], a[ks][1], a[ks][2], a[ks][3],
                     abase + (u32)(row * 128) + cb);
            }
#pragma unroll
            for (int jn = 0; jn < 8; ++jn) {
                int rowb = jn * 16 + lr;
                u32 rba  = bbase + (u32)(rowb * 128);
                u32 xorb = (u32)((rowb & 7) << 4);
#pragma unroll
                for (int ks = 0; ks < 4; ++ks) {
                    u32 bf0, bf1, bf2, bf3;
                    ldm4(bf0, bf1, bf2, bf3,
                         rba + ((u32)(ks * 32 + chi * 16) ^ xorb));
                    mma16816(S[2 * jn],     a[ks][0], a[ks][1], a[ks][2], a[ks][3], bf0, bf2);
                    mma16816(S[2 * jn + 1], a[ks][0], a[ks][1], a[ks][2], a[ks][3], bf1, bf3);
                }
            }
        }

        // ---- mask + online softmax ----
        float rmax0 = -1e30f, rmax1 = -1e30f;
#pragma unroll
        for (int nf = 0; nf < 16; ++nf) {
            int col = kbase + nf * 8 + tg * 2;
            int2 mk0 = *(const int2*)(mask + mrow0 + col);
            int2 mk1 = *(const int2*)(mask + mrow1 + col);
            S[nf][0] += (float)mk0.x * MC;
            S[nf][1] += (float)mk0.y * MC;
            S[nf][2] += (float)mk1.x * MC;
            S[nf][3] += (float)mk1.y * MC;
            rmax0 = fmaxf(rmax0, fmaxf(S[nf][0], S[nf][1]));
            rmax1 = fmaxf(rmax1, fmaxf(S[nf][2], S[nf][3]));
        }
#pragma unroll
        for (int off = 1; off <= 2; off <<= 1) {
            rmax0 = fmaxf(rmax0, __shfl_xor_sync(0xffffffffu, rmax0, off));
            rmax1 = fmaxf(rmax1, __shfl_xor_sync(0xffffffffu, rmax1, off));
        }
        float mn0 = fmaxf(mm0, rmax0), mn1 = fmaxf(mm1, rmax1);
        float al0 = ex2(mm0 - mn0),    al1 = ex2(mm1 - mn1);
        mm0 = mn0; mm1 = mn1;
        float rs0 = 0.f, rs1 = 0.f;
#pragma unroll
        for (int nf = 0; nf < 16; ++nf) {
            S[nf][0] = exp2p(S[nf][0] - mn0);
            S[nf][1] = exp2p(S[nf][1] - mn0);
            S[nf][2] = exp2p(S[nf][2] - mn1);
            S[nf][3] = exp2p(S[nf][3] - mn1);
            rs0 += S[nf][0] + S[nf][1];
            rs1 += S[nf][2] + S[nf][3];
        }
#pragma unroll
        for (int off = 1; off <= 2; off <<= 1) {
            rs0 += __shfl_xor_sync(0xffffffffu, rs0, off);
            rs1 += __shfl_xor_sync(0xffffffffu, rs1, off);
        }
        ll0 = ll0 * al0 + rs0;
        ll1 = ll1 * al1 + rs1;
#pragma unroll
        for (int nf = 0; nf < 8; ++nf) {
            O[nf][0] *= al0; O[nf][1] *= al0;
            O[nf][2] *= al1; O[nf][3] *= al1;
        }

        // ---- O += P V (3-pass split; P frags built in-register) ----
#pragma unroll
        for (int ks2 = 0; ks2 < 8; ++ks2) {
            u32 ahi[4], alo[4];
            split2(S[2 * ks2][0],     S[2 * ks2][1],     ahi[0], alo[0]);
            split2(S[2 * ks2][2],     S[2 * ks2][3],     ahi[1], alo[1]);
            split2(S[2 * ks2 + 1][0], S[2 * ks2 + 1][1], ahi[2], alo[2]);
            split2(S[2 * ks2 + 1][2], S[2 * ks2 + 1][3], ahi[3], alo[3]);
#pragma unroll
            for (int jd = 0; jd < 4; ++jd) {
                int rowd = jd * 16 + lr;
                u32 aoff = (u32)(rowd * 256) +
                           ((u32)(ks2 * 32 + chi * 16) ^ (u32)((rowd & 7) << 4));
                u32 b0, b1, b2, b3;
                ldm4(b0, b1, b2, b3, sb + AVHI + aoff);
                mma16816(O[2 * jd],     ahi[0], ahi[1], ahi[2], ahi[3], b0, b2);
                mma16816(O[2 * jd + 1], ahi[0], ahi[1], ahi[2], ahi[3], b1, b3);
                mma16816(O[2 * jd],     alo[0], alo[1], alo[2], alo[3], b0, b2);
                mma16816(O[2 * jd + 1], alo[0], alo[1], alo[2], alo[3], b1, b3);
                u32 c0, c1, c2, c3;
                ldm4(c0, c1, c2, c3, sb + AVLO + aoff);
                mma16816(O[2 * jd],     ahi[0], ahi[1], ahi[2], ahi[3], c0, c2);
                mma16816(O[2 * jd + 1], ahi[0], ahi[1], ahi[2], ahi[3], c1, c3);
            }
        }
    }

    // ---- write O / l to g_ao ----
    float inv0 = 1.f / ll0, inv1 = 1.f / ll1;
    float* o0p = g_ao + (size_t)(b * Nseq + qbase + qw + g) * Cdim + h * 64;
    float* o1p = o0p + (size_t)8 * Cdim;
#pragma unroll
    for (int nf = 0; nf < 8; ++nf) {
        int col = nf * 8 + tg * 2;
        float2 v0; v0.x = O[nf][0] * inv0; v0.y = O[nf][1] * inv0;
        float2 v1; v1.x = O[nf][2] * inv1; v1.y = O[nf][3] * inv1;
        *(float2*)(o0p + col) = v0;
        *(float2*)(o1p + col) = v1;
    }
}

// ---------------------------------------------------------------------------
extern "C" void kernel_launch(void* const* d_in, const int* in_sizes, int n_in,
                              void* d_out, int out_size) {
    const float* x      = (const float*)d_in[0];
    const int*   mask   = (const int*)  d_in[1];
    const float* qkv_w  = (const float*)d_in[2];
    const float* proj_w = (const float*)d_in[3];
    const float* proj_b = (const float*)d_in[4];
    float*       out    = (float*)d_out;

    cudaFuncSetAttribute(attn_mma,
                         cudaFuncAttributeMaxDynamicSharedMemorySize, ATTN_SMEM);
    cudaFuncSetAttribute(gemm_mma<1>,
                         cudaFuncAttributeMaxDynamicSharedMemorySize, GEMM_SMEM);
    cudaFuncSetAttribute(gemm_mma<2>,
                         cudaFuncAttributeMaxDynamicSharedMemorySize, GEMM_SMEM);

    gemm_mma<1><<<dim3(2304 / 128, 8192 / 128), 256, GEMM_SMEM>>>(x, qkv_w, nullptr,
                                                                  nullptr, 2304);
    attn_mma<<<dim3(Nseq / 128, Bc * Hh), 256, ATTN_SMEM>>>(mask);
    gemm_mma<2><<<dim3(768 / 128, 8192 / 128), 256, GEMM_SMEM>>>(nullptr, proj_w, proj_b,
                                                                 out, 768);
}

// round 8
// speedup vs baseline: 2.3156x; 1.1693x over previous
// v8: precomputed bf16 hi/lo QKV in GEMM1 epilogue (V pre-transposed) +
// cp.async double-buffered attention fills. Compute math identical to v7.
#include <cuda_runtime.h>
#include <cuda_bf16.h>
#include <cstdint>

#define Bc   4
#define Nseq 2048
#define Cdim 768
#define Hh   12
#define Dd   64

using u64 = unsigned long long;
using u32 = unsigned int;

#define QS_CONST 92.33248261972106f    // 64 * log2(e)
#define MC_CONST -1442695.040888963f   // -1e6 * log2(e)

__device__ __forceinline__ float ex2(float x) {
    float y; asm("ex2.approx.f32 %0,%1;" : "=f"(y) : "f"(x)); return y;
}
__device__ __forceinline__ u32 smem_u32(const void* p) {
    u32 a; asm("{ .reg .u64 t; cvta.to.shared.u64 t, %1; cvt.u32.u64 %0, t; }" : "=r"(a) : "l"(p));
    return a;
}
__device__ __forceinline__ void ldm4(u32& r0, u32& r1, u32& r2, u32& r3, u32 addr) {
    asm volatile("ldmatrix.sync.aligned.m8n8.x4.shared.b16 {%0,%1,%2,%3},[%4];"
        : "=r"(r0), "=r"(r1), "=r"(r2), "=r"(r3) : "r"(addr));
}
__device__ __forceinline__ void mma16816(float* c, u32 a0, u32 a1, u32 a2, u32 a3,
                                         u32 b0, u32 b1) {
    asm volatile("mma.sync.aligned.m16n8k16.row.col.f32.bf16.bf16.f32 "
        "{%0,%1,%2,%3},{%4,%5,%6,%7},{%8,%9},{%0,%1,%2,%3};"
        : "+f"(c[0]), "+f"(c[1]), "+f"(c[2]), "+f"(c[3])
        : "r"(a0), "r"(a1), "r"(a2), "r"(a3), "r"(b0), "r"(b1));
}
__device__ __forceinline__ u32 pkbf(float lo, float hi) {
    u32 r; asm("cvt.rn.bf16x2.f32 %0,%1,%2;" : "=r"(r) : "f"(hi), "f"(lo)); return r;
}
__device__ __forceinline__ void split2(float x, float y, u32& hi, u32& lo) {
    hi = pkbf(x, y);
    float hx = __int_as_float(hi << 16);
    float hy = __int_as_float(hi & 0xFFFF0000u);
    lo = pkbf(x - hx, y - hy);
}
// FFMA-only exp2 for x <= 0 (clamped); rel err ~4e-5
__device__ __forceinline__ float exp2p(float x) {
    x = fmaxf(x, -126.0f);
    float t = x + 12582912.0f;
    int  k  = __float_as_int(t) - 0x4B400000;
    float xf = x - (t - 12582912.0f);
    float p = 0.0096180f;
    p = p * xf + 0.0555041f;
    p = p * xf + 0.2402265f;
    p = p * xf + 0.6931472f;
    p = p * xf + 1.0f;
    return p * __int_as_float((k + 127) << 23);
}
__device__ __forceinline__ void cpa16(u32 dst, const void* src) {
    asm volatile("cp.async.cg.shared.global [%0], [%1], 16;" :: "r"(dst), "l"(src) : "memory");
}
#define CP_COMMIT() asm volatile("cp.async.commit_group;" ::: "memory")
#define CP_WAIT(n)  asm volatile("cp.async.wait_group %0;" :: "n"(n) : "memory")

// Scratch: bf16 hi/lo QKV (Q pre-scaled; V pre-transposed) + fp32 attn out
__device__ __nv_bfloat16 g_qhi[(size_t)48 * 2048 * 64];
__device__ __nv_bfloat16 g_qlo[(size_t)48 * 2048 * 64];
__device__ __nv_bfloat16 g_khi[(size_t)48 * 2048 * 64];
__device__ __nv_bfloat16 g_klo[(size_t)48 * 2048 * 64];
__device__ __nv_bfloat16 g_vthi[(size_t)48 * 64 * 2048];   // [bh][d][n]
__device__ __nv_bfloat16 g_vtlo[(size_t)48 * 64 * 2048];
__device__ float g_ao[(size_t)Bc * Nseq * Cdim];           // [B][N][C]

// ===========================================================================
// HMMA split-bf16 GEMM NT (round-6 structure; MODE 1 epilogue -> bf16 arrays)
// ===========================================================================
#define TILE_B 16384
#define STG_B  (4 * TILE_B)
#define GEMM_SMEM (2 * STG_B)

__device__ __forceinline__ void fill_pair(const float* __restrict__ src, char* hi,
                                          char* lo, int kbase, int t) {
#pragma unroll
    for (int it = 0; it < 8; ++it) {
        int f4  = t + it * 256;
        int row = f4 >> 4;
        int c4  = (f4 & 15) << 2;
        float4 v = *(const float4*)(src + (size_t)row * 768 + kbase + c4);
        u32 h01, l01, h23, l23;
        split2(v.x, v.y, h01, l01);
        split2(v.z, v.w, h23, l23);
        u32 off = (u32)(row * 128 + c4 * 2);
        u32 sw  = off ^ ((off >> 3) & 0x70);
        uint2 uh; uh.x = h01; uh.y = h23;
        uint2 ul; ul.x = l01; ul.y = l23;
        *(uint2*)(hi + sw) = uh;
        *(uint2*)(lo + sw) = ul;
    }
}

template<int MODE>
__global__ void __launch_bounds__(256) gemm_mma(const float* __restrict__ A_,
                                                const float* __restrict__ Bw,
                                                const float* __restrict__ bias,
                                                float* __restrict__ C, int Nn) {
    extern __shared__ __align__(1024) char smem[];
    const u32 sb   = smem_u32(smem);
    const int t    = threadIdx.x, lane = t & 31, wid = t >> 5;
    const int i0   = blockIdx.y * 128, j0 = blockIdx.x * 128;
    const float* __restrict__ Arow = ((MODE == 2) ? g_ao : A_) + (size_t)i0 * 768;
    const float* __restrict__ Brow = Bw + (size_t)j0 * 768;

    const int m0  = (wid >> 2) * 64;
    const int n0  = (wid & 3) * 32;
    const int lr  = lane & 15;
    const int chi = lane >> 4;
    const u32 xorv = (u32)((lane & 7) << 4);

    float acc[4][4][4];
#pragma unroll
    for (int i = 0; i < 4; i++)
#pragma unroll
        for (int j = 0; j < 4; j++)
#pragma unroll
            for (int k = 0; k < 4; k++) acc[i][j][k] = 0.f;

    fill_pair(Arow, smem + 0,          smem + TILE_B,     0, t);
    fill_pair(Brow, smem + 2 * TILE_B, smem + 3 * TILE_B, 0, t);
    __syncthreads();

    for (int kc = 0; kc < 12; ++kc) {
        const int st = kc & 1;
        if (kc + 1 < 12) {
            char* nb = smem + (st ^ 1) * STG_B;
            fill_pair(Arow, nb,              nb + TILE_B,     (kc + 1) * 64, t);
            fill_pair(Brow, nb + 2 * TILE_B, nb + 3 * TILE_B, (kc + 1) * 64, t);
        }
        __syncthreads();

        const u32 base = sb + st * STG_B;
#pragma unroll
        for (int s = 0; s < 4; ++s) {
            const u32 colterm = ((u32)((2 * s + chi) << 4)) ^ xorv;
            u32 ah[4][4], al[4][4];
#pragma unroll
            for (int i = 0; i < 4; i++) {
                u32 ra = base + (u32)((m0 + i * 16 + lr) * 128) + colterm;
                ldm4(ah[i][0], ah[i][1], ah[i][2], ah[i][3], ra);
                ldm4(al[i][0], al[i][1], al[i][2], al[i][3], ra + TILE_B);
            }
            u32 bh[8], bl[8];
#pragma unroll
            for (int j = 0; j < 2; j++) {
                u32 rb = base + 2 * TILE_B + (u32)((n0 + j * 16 + lr) * 128) + colterm;
                ldm4(bh[j * 4 + 0], bh[j * 4 + 1], bh[j * 4 + 2], bh[j * 4 + 3], rb);
                ldm4(bl[j * 4 + 0], bl[j * 4 + 1], bl[j * 4 + 2], bl[j * 4 + 3], rb + TILE_B);
            }
#pragma unroll
            for (int i = 0; i < 4; i++)
#pragma unroll
                for (int jj = 0; jj < 4; jj++) {
                    int j4 = (jj >> 1) * 4 + (jj & 1);
                    mma16816(acc[i][jj], ah[i][0], ah[i][1], ah[i][2], ah[i][3],
                             bh[j4], bh[j4 + 2]);
                    mma16816(acc[i][jj], ah[i][0], ah[i][1], ah[i][2], ah[i][3],
                             bl[j4], bl[j4 + 2]);
                    mma16816(acc[i][jj], al[i][0], al[i][1], al[i][2], al[i][3],
                             bh[j4], bh[j4 + 2]);
                }
        }
        __syncthreads();
    }

#pragma unroll
    for (int i = 0; i < 4; i++) {
        int r0 = m0 + i * 16 + (lane >> 2);
#pragma unroll
        for (int jj = 0; jj < 4; jj++) {
            int col = n0 + jj * 8 + 2 * (lane & 3);
#pragma unroll
            for (int half = 0; half < 2; half++) {
                int gi = i0 + r0 + half * 8;
                int gj = j0 + col;
                float2 v;
                v.x = acc[i][jj][half * 2 + 0];
                v.y = acc[i][jj][half * 2 + 1];
                if (MODE == 1) {
                    int b = gi >> 11, n = gi & 2047;
                    int three = gj / 768, rem = gj - three * 768;
                    int hh = rem >> 6, d = rem & 63;
                    int bhI = b * 12 + hh;
                    if (three < 2) {
                        float sc = (three == 0) ? QS_CONST : 1.0f;
                        u32 hi, lo;
                        split2(v.x * sc, v.y * sc, hi, lo);
                        size_t idx = ((size_t)bhI * 2048 + n) * 64 + d;
                        __nv_bfloat16* ph = (three == 0) ? g_qhi : g_khi;
                        __nv_bfloat16* pl = (three == 0) ? g_qlo : g_klo;
                        *(u32*)(ph + idx) = hi;
                        *(u32*)(pl + idx) = lo;
                    } else {
                        size_t b0 = ((size_t)bhI * 64 + d) * 2048 + n;
                        __nv_bfloat16 hx = __float2bfloat16(v.x);
                        g_vthi[b0] = hx;
                        g_vtlo[b0] = __float2bfloat16(v.x - __bfloat162float(hx));
                        __nv_bfloat16 hy = __float2bfloat16(v.y);
                        g_vthi[b0 + 2048] = hy;
                        g_vtlo[b0 + 2048] = __float2bfloat16(v.y - __bfloat162float(hy));
                    }
                } else {
                    v.x += bias[gj];
                    v.y += bias[gj + 1];
                    *(float2*)(C + (size_t)gi * Nn + gj) = v;
                }
            }
        }
    }
}

// ===========================================================================
// HMMA flash attention with cp.async double-buffered fills.
// smem: Q hi/lo 32KB + 2 stages x (Khi,Klo,Vthi,Vtlo) 64KB = 160KB.
// ===========================================================================
#define AQHI 0
#define AQLO 16384
#define STAGE0 32768
#define STG_SZ 65536
#define SKHI 0
#define SKLO 16384
#define SVHI 32768
#define SVLO 49152
#define ATTN_SMEM (STAGE0 + 2 * STG_SZ)

__device__ __forceinline__ void attn_issue(u32 stg, int kbase, int t,
        const __nv_bfloat16* khi, const __nv_bfloat16* klo,
        const __nv_bfloat16* vthi, const __nv_bfloat16* vtlo) {
#pragma unroll
    for (int it = 0; it < 4; ++it) {
        int slot = t + it * 256;           // 1024 slots
        int row  = slot >> 3, c = slot & 7;
        u32 dk = stg + SKHI + (u32)(row * 128) + (u32)((c * 16) ^ ((row & 7) << 4));
        size_t so = (size_t)(kbase + row) * 64 + c * 8;
        cpa16(dk,                 khi + so);
        cpa16(dk + (SKLO - SKHI), klo + so);
    }
#pragma unroll
    for (int it = 0; it < 4; ++it) {
        int slot = t + it * 256;
        int row  = slot >> 4, c = slot & 15;   // 64 rows x 16 chunks
        u32 dv = stg + SVHI + (u32)(row * 256) + (u32)((c * 16) ^ ((row & 7) << 4));
        size_t so = (size_t)row * 2048 + kbase + c * 8;
        cpa16(dv,                 vthi + so);
        cpa16(dv + (SVLO - SVHI), vtlo + so);
    }
}

__global__ void __launch_bounds__(256) attn_mma(const int* __restrict__ mask) {
    extern __shared__ __align__(1024) char smem[];
    const u32 sb = smem_u32(smem);
    const int t  = threadIdx.x, lane = t & 31, w = t >> 5;
    const int g  = lane >> 2, tg = lane & 3;
    const int lr = lane & 15, chi = lane >> 4;
    const int bh = blockIdx.y;
    const int b  = bh / Hh, h = bh - b * Hh;
    const int qbase = blockIdx.x * 128;
    const int qw = w * 16;

    const __nv_bfloat16* qhi  = g_qhi  + (size_t)bh * 2048 * 64;
    const __nv_bfloat16* qlo  = g_qlo  + (size_t)bh * 2048 * 64;
    const __nv_bfloat16* khi  = g_khi  + (size_t)bh * 2048 * 64;
    const __nv_bfloat16* klo  = g_klo  + (size_t)bh * 2048 * 64;
    const __nv_bfloat16* vthi = g_vthi + (size_t)bh * 64 * 2048;
    const __nv_bfloat16* vtlo = g_vtlo + (size_t)bh * 64 * 2048;

    // prologue: Q tiles + chunk0 (group 0), chunk1 (group 1)
#pragma unroll
    for (int it = 0; it < 4; ++it) {
        int slot = t + it * 256;
        int row  = slot >> 3, c = slot & 7;
        u32 dq = sb + AQHI + (u32)(row * 128) + (u32)((c * 16) ^ ((row & 7) << 4));
        size_t so = (size_t)(qbase + row) * 64 + c * 8;
        cpa16(dq,                 qhi + so);
        cpa16(dq + (AQLO - AQHI), qlo + so);
    }
    attn_issue(sb + STAGE0, 0, t, khi, klo, vthi, vtlo);
    CP_COMMIT();
    attn_issue(sb + STAGE0 + STG_SZ, 128, t, khi, klo, vthi, vtlo);
    CP_COMMIT();

    float O[8][4];
#pragma unroll
    for (int i = 0; i < 8; i++)
#pragma unroll
        for (int j = 0; j < 4; j++) O[i][j] = 0.f;
    float mm0 = -1e30f, mm1 = -1e30f, ll0 = 0.f, ll1 = 0.f;
    u32 qh[4][4], ql[4][4];

    const int mrow0 = (qbase + qw + g) * 2048;
    const int mrow1 = mrow0 + 8 * 2048;

    for (int kc = 0; kc < 16; ++kc) {
        const int kbase = kc * 128;
        const u32 stg = sb + STAGE0 + (u32)((kc & 1) * STG_SZ);
        if (kc < 15) { CP_WAIT(1); } else { CP_WAIT(0); }
        __syncthreads();

        if (kc == 0) {
            int row = qw + lr;
            u32 xq = (u32)((row & 7) << 4);
#pragma unroll
            for (int ks = 0; ks < 4; ++ks) {
                u32 cb = (u32)((ks * 32 + chi * 16)) ^ xq;
                u32 ra = sb + AQHI + (u32)(row * 128) + cb;
                ldm4(qh[ks][0], qh[ks][1], qh[ks][2], qh[ks][3], ra);
                ldm4(ql[ks][0], ql[ks][1], ql[ks][2], ql[ks][3], ra + (AQLO - AQHI));
            }
        }

        // ---- S = Q K^T (fused 3-pass split) ----
        float S[16][4];
#pragma unroll
        for (int i = 0; i < 16; i++)
#pragma unroll
            for (int j = 0; j < 4; j++) S[i][j] = 0.f;

#pragma unroll
        for (int jn = 0; jn < 8; ++jn) {
            int rowb = jn * 16 + lr;
            u32 rba  = stg + SKHI + (u32)(rowb * 128);
            u32 xorb = (u32)((rowb & 7) << 4);
#pragma unroll
            for (int ks = 0; ks < 4; ++ks) {
                u32 off = ((u32)(ks * 32 + chi * 16)) ^ xorb;
                u32 bh0, bh1, bh2, bh3, bl0, bl1, bl2, bl3;
                ldm4(bh0, bh1, bh2, bh3, rba + off);
                ldm4(bl0, bl1, bl2, bl3, rba + (SKLO - SKHI) + off);
                mma16816(S[2 * jn],     qh[ks][0], qh[ks][1], qh[ks][2], qh[ks][3], bh0, bh2);
                mma16816(S[2 * jn + 1], qh[ks][0], qh[ks][1], qh[ks][2], qh[ks][3], bh1, bh3);
                mma16816(S[2 * jn],     qh[ks][0], qh[ks][1], qh[ks][2], qh[ks][3], bl0, bl2);
                mma16816(S[2 * jn + 1], qh[ks][0], qh[ks][1], qh[ks][2], qh[ks][3], bl1, bl3);
                mma16816(S[2 * jn],     ql[ks][0], ql[ks][1], ql[ks][2], ql[ks][3], bh0, bh2);
                mma16816(S[2 * jn + 1], ql[ks][0], ql[ks][1], ql[ks][2], ql[ks][3], bh1, bh3);
            }
        }

        // ---- mask + online softmax ----
        float rmax0 = -1e30f, rmax1 = -1e30f;
#pragma unroll
        for (int nf = 0; nf < 16; ++nf) {
            int col = kbase + nf * 8 + tg * 2;
            int2 mk0 = *(const int2*)(mask + mrow0 + col);
            int2 mk1 = *(const int2*)(mask + mrow1 + col);
            S[nf][0] += (float)mk0.x * MC_CONST;
            S[nf][1] += (float)mk0.y * MC_CONST;
            S[nf][2] += (float)mk1.x * MC_CONST;
            S[nf][3] += (float)mk1.y * MC_CONST;
            rmax0 = fmaxf(rmax0, fmaxf(S[nf][0], S[nf][1]));
            rmax1 = fmaxf(rmax1, fmaxf(S[nf][2], S[nf][3]));
        }
#pragma unroll
        for (int off = 1; off <= 2; off <<= 1) {
            rmax0 = fmaxf(rmax0, __shfl_xor_sync(0xffffffffu, rmax0, off));
            rmax1 = fmaxf(rmax1, __shfl_xor_sync(0xffffffffu, rmax1, off));
        }
        float mn0 = fmaxf(mm0, rmax0), mn1 = fmaxf(mm1, rmax1);
        float al0 = ex2(mm0 - mn0),    al1 = ex2(mm1 - mn1);
        mm0 = mn0; mm1 = mn1;
        float rs0 = 0.f, rs1 = 0.f;
#pragma unroll
        for (int nf = 0; nf < 16; ++nf) {
            S[nf][0] = exp2p(S[nf][0] - mn0);
            S[nf][1] = exp2p(S[nf][1] - mn0);
            S[nf][2] = exp2p(S[nf][2] - mn1);
            S[nf][3] = exp2p(S[nf][3] - mn1);
            rs0 += S[nf][0] + S[nf][1];
            rs1 += S[nf][2] + S[nf][3];
        }
#pragma unroll
        for (int off = 1; off <= 2; off <<= 1) {
            rs0 += __shfl_xor_sync(0xffffffffu, rs0, off);
            rs1 += __shfl_xor_sync(0xffffffffu, rs1, off);
        }
        ll0 = ll0 * al0 + rs0;
        ll1 = ll1 * al1 + rs1;
#pragma unroll
        for (int nf = 0; nf < 8; ++nf) {
            O[nf][0] *= al0; O[nf][1] *= al0;
            O[nf][2] *= al1; O[nf][3] *= al1;
        }

        // ---- O += P V (3-pass; P frags in-register) ----
#pragma unroll
        for (int ks2 = 0; ks2 < 8; ++ks2) {
            u32 ahi[4], alo[4];
            split2(S[2 * ks2][0],     S[2 * ks2][1],     ahi[0], alo[0]);
            split2(S[2 * ks2][2],     S[2 * ks2][3],     ahi[1], alo[1]);
            split2(S[2 * ks2 + 1][0], S[2 * ks2 + 1][1], ahi[2], alo[2]);
            split2(S[2 * ks2 + 1][2], S[2 * ks2 + 1][3], ahi[3], alo[3]);
#pragma unroll
            for (int jd = 0; jd < 4; ++jd) {
                int rowd = jd * 16 + lr;
                u32 aoff = (u32)(rowd * 256) +
                           (((u32)(ks2 * 32 + chi * 16)) ^ (u32)((rowd & 7) << 4));
                u32 b0, b1, b2, b3;
                ldm4(b0, b1, b2, b3, stg + SVHI + aoff);
                mma16816(O[2 * jd],     ahi[0], ahi[1], ahi[2], ahi[3], b0, b2);
                mma16816(O[2 * jd + 1], ahi[0], ahi[1], ahi[2], ahi[3], b1, b3);
                mma16816(O[2 * jd],     alo[0], alo[1], alo[2], alo[3], b0, b2);
                mma16816(O[2 * jd + 1], alo[0], alo[1], alo[2], alo[3], b1, b3);
                u32 c0, c1, c2, c3;
                ldm4(c0, c1, c2, c3, stg + SVLO + aoff);
                mma16816(O[2 * jd],     ahi[0], ahi[1], ahi[2], ahi[3], c0, c2);
                mma16816(O[2 * jd + 1], ahi[0], ahi[1], ahi[2], ahi[3], c1, c3);
            }
        }

        __syncthreads();   // all warps done reading stage before refill
        if (kc + 2 < 16) {
            attn_issue(stg, (kc + 2) * 128, t, khi, klo, vthi, vtlo);
            CP_COMMIT();
        }
    }

    // ---- write O / l to g_ao ----
    float inv0 = 1.f / ll0, inv1 = 1.f / ll1;
    float* o0p = g_ao + (size_t)(b * Nseq + qbase + qw + g) * Cdim + h * 64;
    float* o1p = o0p + (size_t)8 * Cdim;
#pragma unroll
    for (int nf = 0; nf < 8; ++nf) {
        int col = nf * 8 + tg * 2;
        float2 v0; v0.x = O[nf][0] * inv0; v0.y = O[nf][1] * inv0;
        float2 v1; v1.x = O[nf][2] * inv1; v1.y = O[nf][3] * inv1;
        *(float2*)(o0p + col) = v0;
        *(float2*)(o1p + col) = v1;
    }
}

// ---------------------------------------------------------------------------
extern "C" void kernel_launch(void* const* d_in, const int* in_sizes, int n_in,
                              void* d_out, int out_size) {
    const float* x      = (const float*)d_in[0];
    const int*   mask   = (const int*)  d_in[1];
    const float* qkv_w  = (const float*)d_in[2];
    const float* proj_w = (const float*)d_in[3];
    const float* proj_b = (const float*)d_in[4];
    float*       out    = (float*)d_out;

    cudaFuncSetAttribute(attn_mma,
                         cudaFuncAttributeMaxDynamicSharedMemorySize, ATTN_SMEM);
    cudaFuncSetAttribute(gemm_mma<1>,
                         cudaFuncAttributeMaxDynamicSharedMemorySize, GEMM_SMEM);
    cudaFuncSetAttribute(gemm_mma<2>,
                         cudaFuncAttributeMaxDynamicSharedMemorySize, GEMM_SMEM);

    gemm_mma<1><<<dim3(2304 / 128, 8192 / 128), 256, GEMM_SMEM>>>(x, qkv_w, nullptr,
                                                                  nullptr, 2304);
    attn_mma<<<dim3(Nseq / 128, Bc * Hh), 256, ATTN_SMEM>>>(mask);
    gemm_mma<2><<<dim3(768 / 128, 8192 / 128), 256, GEMM_SMEM>>>(nullptr, proj_w, proj_b,
                                                                 out, 768);
}